// round 15
// baseline (speedup 1.0000x reference)
#include <cuda_runtime.h>
#include <cstdint>

// ---------------------------------------------------------------------------
// GenerativeUpsample: per-batch kth-smallest threshold on pred, prune fea.
//   fea:  [N, 64] f32   d_in[0]
//   pred: [N, 1]  f32   d_in[1]
//   bid:  [N]     i32   d_in[2]  (sorted, values in [0,B))
//   tgt:  [B]     i32   d_in[3]
// out: [N*64] pruned fea, then (if room) [N] keep as 0/1 float.
//
// Exact select on monotone uint key of pred:
//   hist1 (top16) -> coarse -> walk1
//   -> fused prune (resolves keep from top16 vs selBin; streams fea;
//      stashes rare in-bin "deferred" rows, writes zeros for them)
//   -> final (smem radix over deferred keys; repairs deferred rows).
// 5 launches. Scratch zeroed at load + re-zeroed in-pipeline for graph replay.
// ---------------------------------------------------------------------------

#define MAXB 8
#define NBIN 65536
#define NSEG 64
#define SEGBINS 1024
#define CAP 8192

__device__ __align__(16) unsigned g_hist1[MAXB * NBIN];
__device__ __align__(16) unsigned g_vals[MAXB * CAP];   // deferred keys
__device__ __align__(16) int      g_rows[MAXB * CAP];   // their row indices
__device__ unsigned g_cnt[MAXB];
__device__ unsigned g_seg[MAXB * NSEG];
__device__ unsigned g_selBin[MAXB];
__device__ unsigned g_selRank[MAXB];
__device__ int      g_active[MAXB];

__device__ __forceinline__ unsigned f2key(float f) {
    unsigned u = __float_as_uint(f);
    return (u & 0x80000000u) ? ~u : (u | 0x80000000u);
}

// block-wide (256 thr) exclusive scan; wsum = 8-word smem scratch.
__device__ __forceinline__ unsigned scan_excl(unsigned val, int tid,
                                              unsigned* wsum) {
    int lane = tid & 31, wid = tid >> 5;
    unsigned x = val;
    #pragma unroll
    for (int d = 1; d < 32; d <<= 1) {
        unsigned y = __shfl_up_sync(0xFFFFFFFFu, x, d);
        if (lane >= d) x += y;
    }
    if (lane == 31) wsum[wid] = x;
    __syncthreads();
    if (tid == 0) {
        unsigned a = 0;
        #pragma unroll
        for (int w = 0; w < 8; w++) { unsigned t = wsum[w]; wsum[w] = a; a += t; }
    }
    __syncthreads();
    return wsum[wid] + x - val;
}

// -------- pass 1: top-16-bit histogram; batch from bid loads ---------------
__global__ void k_hist1(const float4* __restrict__ pred4,
                        const uint4* __restrict__ bid4, int n4) {
    for (int i4 = blockIdx.x * blockDim.x + threadIdx.x; i4 < n4;
         i4 += gridDim.x * blockDim.x) {
        float4 p = pred4[i4];
        uint4 bb = bid4[i4];
        float pv[4] = {p.x, p.y, p.z, p.w};
        unsigned bv[4] = {bb.x, bb.y, bb.z, bb.w};
        #pragma unroll
        for (int j = 0; j < 4; j++)
            atomicAdd(&g_hist1[bv[j] * NBIN + (f2key(pv[j]) >> 16)], 1u);
    }
}

// -------- coarse segment sums: 8 batches x 64 segs = 512 blocks ------------
__global__ void k_coarse() {
    int b = blockIdx.x >> 6;
    int s = blockIdx.x & 63;
    const uint4* h4 = (const uint4*)&g_hist1[b * NBIN + s * SEGBINS];
    uint4 v = h4[threadIdx.x];
    unsigned sum = v.x + v.y + v.z + v.w;
    #pragma unroll
    for (int d = 16; d > 0; d >>= 1) sum += __shfl_down_sync(0xFFFFFFFFu, sum, d);
    __shared__ unsigned ws[8];
    if ((threadIdx.x & 31) == 0) ws[threadIdx.x >> 5] = sum;
    __syncthreads();
    if (threadIdx.x == 0) {
        unsigned t = 0;
        #pragma unroll
        for (int w = 0; w < 8; w++) t += ws[w];
        g_seg[b * NSEG + s] = t;
    }
}

// -------- walk1: pick level-1 bin; count derived from seg totals -----------
__global__ void k_walk1(const int* __restrict__ tgt) {
    int b = blockIdx.x;
    int tid = threadIdx.x;
    __shared__ unsigned wsum[8];
    __shared__ unsigned stotal;
    __shared__ int ssegi;
    __shared__ unsigned srank2;

    unsigned v = (tid < NSEG) ? g_seg[b * NSEG + tid] : 0u;
    unsigned e = scan_excl(v, tid, wsum);
    if (tid == NSEG - 1) stotal = e + v;
    __syncthreads();

    int nn = (int)stotal;
    int t = tgt[b];
    if (nn <= t) {
        if (tid == 0) {
            g_active[b] = 0;
            g_selBin[b] = 0xFFFFFFFFu;  // matches no top16 -> keep all
            g_selRank[b] = 0;
        }
        return;
    }
    unsigned rank = (unsigned)(nn - t - 1);  // 0-indexed kth
    if (tid == 0) g_active[b] = 1;
    if (rank >= e && rank < e + v) { ssegi = tid; srank2 = rank - e; }
    __syncthreads();

    const uint4* h4 = (const uint4*)&g_hist1[b * NBIN + ssegi * SEGBINS];
    uint4 q = h4[tid];
    unsigned v2 = q.x + q.y + q.z + q.w;
    unsigned e2 = scan_excl(v2, tid, wsum);
    unsigned r2 = srank2;
    if (r2 >= e2 && r2 < e2 + v2) {
        unsigned rr = r2 - e2;
        unsigned bvals[4] = {q.x, q.y, q.z, q.w};
        int j = 0;
        while (rr >= bvals[j]) { rr -= bvals[j]; j++; }
        g_selBin[b] = (unsigned)(ssegi * SEGBINS + tid * 4 + j);
        g_selRank[b] = rr;
    }
}

// -------- fused prune: resolve keep inline, stream fea, stash deferred -----
__global__ void k_prune(const float4* __restrict__ fea4,
                        const float* __restrict__ pred,
                        const int* __restrict__ bid,
                        float4* __restrict__ out4,
                        float* __restrict__ out_keep,
                        int total2, int writeKeep) {
    __shared__ unsigned ssel[MAXB];
    if (threadIdx.x < MAXB) ssel[threadIdx.x] = g_selBin[threadIdx.x];
    __syncthreads();

    int gid = blockIdx.x * blockDim.x + threadIdx.x;

    // re-zero hist1 for next invocation (consumed by coarse/walk1 already)
    {
        const int ZW = (MAXB * NBIN) / 4;  // uint4 words in g_hist1
        if (gid < ZW)
            ((uint4*)g_hist1)[gid] = make_uint4(0u, 0u, 0u, 0u);
    }

    if (gid >= total2) return;
    int row = gid >> 3;  // 8 threads per 64-wide row (2 float4 each)
    int b = bid[row];
    unsigned key = f2key(pred[row]);
    unsigned top = key >> 16;
    unsigned sel = ssel[b];            // inactive: 0xFFFFFFFF (never matches)
    bool keep = top > sel && sel != 0xFFFFFFFFu;
    if (sel == 0xFFFFFFFFu) keep = true;              // inactive -> keep all
    bool deferred = (top == sel);

    if (deferred && ((gid & 7) == 0)) {  // one stash per row
        unsigned idx = atomicAdd(&g_cnt[b], 1u);
        if (idx < CAP) {
            g_vals[b * CAP + idx] = key;
            g_rows[b * CAP + idx] = row;
        }
    }

    float4 v0 = make_float4(0.f, 0.f, 0.f, 0.f);
    float4 v1 = v0;
    if (keep) {  // dropped/deferred rows: zeros (deferred repaired by final)
        v0 = __ldcs(&fea4[2 * gid]);
        v1 = __ldcs(&fea4[2 * gid + 1]);
    }
    __stcs(&out4[2 * gid], v0);
    __stcs(&out4[2 * gid + 1], v1);
    if (writeKeep && ((gid & 7) == 0)) out_keep[row] = keep ? 1.0f : 0.0f;
}

// -------- final: threshold from deferred keys; repair deferred rows --------
__global__ void k_final(const float4* __restrict__ fea4,
                        float4* __restrict__ out4,
                        float* __restrict__ out_keep, int writeKeep) {
    int b = blockIdx.x;
    int tid = threadIdx.x;  // 256 threads
    __shared__ unsigned svals[CAP];   // low-16 bits of deferred keys
    __shared__ int srows[CAP];
    __shared__ unsigned shist[256];
    __shared__ unsigned wsum[8];
    __shared__ int sb1;
    __shared__ unsigned srank2;
    __shared__ unsigned stlow;

    int act = g_active[b];
    int cnt = act ? (int)min(g_cnt[b], (unsigned)CAP) : 0;
    unsigned rank = g_selRank[b];
    if (tid == 0) g_cnt[b] = 0u;  // reset for next invocation
    if (!act) return;             // nothing deferred for inactive batches

    for (int i = tid; i < cnt; i += 256) {
        svals[i] = g_vals[b * CAP + i] & 0xFFFFu;
        srows[i] = g_rows[b * CAP + i];
    }
    shist[tid] = 0u;
    __syncthreads();

    // stage 1: histogram of bits [8:16)
    for (int i = tid; i < cnt; i += 256)
        atomicAdd(&shist[svals[i] >> 8], 1u);
    __syncthreads();
    unsigned v = shist[tid];
    unsigned e = scan_excl(v, tid, wsum);
    if (rank >= e && rank < e + v) { sb1 = tid; srank2 = rank - e; }
    __syncthreads();
    int b1 = sb1;
    unsigned rank2 = srank2;

    // stage 2: histogram of bits [0:8) among elements with byte1 == b1
    shist[tid] = 0u;
    __syncthreads();
    for (int i = tid; i < cnt; i += 256)
        if ((int)(svals[i] >> 8) == b1) atomicAdd(&shist[svals[i] & 0xFFu], 1u);
    __syncthreads();
    v = shist[tid];
    e = scan_excl(v, tid, wsum);
    if (rank2 >= e && rank2 < e + v)
        stlow = ((unsigned)b1 << 8) | (unsigned)tid;  // low-16 threshold
    __syncthreads();

    // repair deferred rows: keep iff low16 strictly above threshold low16
    unsigned tlow = stlow;
    int totalE = cnt * 16;  // 16 float4 per row
    for (int ei = tid; ei < totalE; ei += 256) {
        int i = ei >> 4;
        int col = ei & 15;
        int row = srows[i];
        bool keep = svals[i] > tlow;
        float4 vv = make_float4(0.f, 0.f, 0.f, 0.f);
        if (keep) vv = fea4[row * 16 + col];
        out4[row * 16 + col] = vv;
        if (writeKeep && col == 0) out_keep[row] = keep ? 1.0f : 0.0f;
    }
}

extern "C" void kernel_launch(void* const* d_in, const int* in_sizes, int n_in,
                              void* d_out, int out_size) {
    const float* fea  = (const float*)d_in[0];
    const float* pred = (const float*)d_in[1];
    const int*   bid  = (const int*)d_in[2];
    const int*   tgt  = (const int*)d_in[3];
    const int n = in_sizes[1];      // N points
    const int C = in_sizes[0] / n;  // 64

    float* out_fea  = (float*)d_out;
    int writeKeep = (out_size >= n * C + n) ? 1 : 0;
    float* out_keep = out_fea + (size_t)n * C;

    int n4 = n / 4;
    k_hist1<<<(n4 + 255) / 256, 256>>>((const float4*)pred,
                                       (const uint4*)bid, n4);
    k_coarse<<<MAXB * NSEG, 256>>>();
    k_walk1<<<MAXB, 256>>>(tgt);

    int total2 = n * (C / 8);  // ILP=2 work items
    k_prune<<<(total2 + 255) / 256, 256>>>((const float4*)fea, pred, bid,
                                           (float4*)d_out, out_keep,
                                           total2, writeKeep);
    k_final<<<MAXB, 256>>>((const float4*)fea, (float4*)d_out, out_keep,
                           writeKeep);
}